// round 13
// baseline (speedup 1.0000x reference)
#include <cuda_runtime.h>
#include <cuda_bf16.h>
#include <cstdint>

// Problem constants (fixed by the reference)
#define NNODES 50000
#define NEDGES 600000
#define DIM    128
#define OUTD   64

#define SCAN_BLOCKS 49           // 49 * 1024 = 50176 >= NNODES
#define NPAD (SCAN_BLOCKS * 1024)

// Scratch (no cudaMalloc allowed)
__device__ float g_m[(size_t)NNODES * DIM];   // GEMM output  (25.6 MB)
__device__ float g_h[(size_t)NNODES * DIM];   // gather dest  (25.6 MB)
__device__ int   g_is64;                      // edge_index dtype flag

// CSR-by-dst scratch
__device__ int g_deg[NPAD];
__device__ int g_excl[NPAD];                  // per-block exclusive scan
__device__ int g_bsum[SCAN_BLOCKS];
__device__ int g_bpre[SCAN_BLOCKS + 1];
__device__ int g_row_start[NNODES + 1];
__device__ int g_cursor[NNODES];
__device__ int g_csr_src[NEDGES];

// ---------------------------------------------------------------------------
// Detect whether edge_index is int64 or int32.
// int64 values in [0, 50000): every odd int32 word is 0 (little-endian).
// ---------------------------------------------------------------------------
__global__ void detect_idx_width_kernel(const int* __restrict__ ei32) {
    if (threadIdx.x == 0 && blockIdx.x == 0) {
        int acc = 0;
        #pragma unroll
        for (int i = 0; i < 16; i++) acc |= ei32[2 * i + 1];
        g_is64 = (acc == 0) ? 1 : 0;
    }
}

__device__ __forceinline__ int load_idx(const void* ei_raw, int E, int half, int e) {
    if (g_is64) {
        const long long* ei = (const long long*)ei_raw;
        return (int)__ldg(ei + (size_t)half * E + e);
    } else {
        const int* ei = (const int*)ei_raw;
        return __ldg(ei + (size_t)half * E + e);
    }
}

// ---------------------------------------------------------------------------
// CSR build kernels
// ---------------------------------------------------------------------------
__global__ void zero_deg_kernel() {
    int i = blockIdx.x * blockDim.x + threadIdx.x;
    if (i < NPAD) g_deg[i] = 0;
}

__global__ __launch_bounds__(256)
void hist_kernel(const void* __restrict__ ei_raw, int E) {
    int e = blockIdx.x * blockDim.x + threadIdx.x;
    if (e >= E) return;
    int dst = load_idx(ei_raw, E, 1, e);
    atomicAdd(&g_deg[dst], 1);
}

// per-1024-block inclusive scan of g_deg (Hillis-Steele); store exclusive.
__global__ __launch_bounds__(1024)
void scan1_kernel() {
    __shared__ int sm[1024];
    int i = blockIdx.x * 1024 + threadIdx.x;
    int v = g_deg[i];
    sm[threadIdx.x] = v;
    __syncthreads();
    #pragma unroll
    for (int off = 1; off < 1024; off <<= 1) {
        int t = (threadIdx.x >= off) ? sm[threadIdx.x - off] : 0;
        __syncthreads();
        sm[threadIdx.x] += t;
        __syncthreads();
    }
    g_excl[i] = sm[threadIdx.x] - v;
    if (threadIdx.x == 1023) g_bsum[blockIdx.x] = sm[1023];
}

__global__ void scan2_kernel() {
    if (threadIdx.x == 0 && blockIdx.x == 0) {
        int run = 0;
        #pragma unroll
        for (int b = 0; b < SCAN_BLOCKS; b++) {
            g_bpre[b] = run;
            run += g_bsum[b];
        }
        g_bpre[SCAN_BLOCKS] = run;
        g_row_start[NNODES] = run;   // == NEDGES
    }
}

__global__ __launch_bounds__(1024)
void scan3_kernel() {
    int i = blockIdx.x * 1024 + threadIdx.x;
    if (i < NNODES) {
        int rs = g_excl[i] + g_bpre[blockIdx.x];
        g_row_start[i] = rs;
        g_cursor[i]    = rs;
    }
}

__global__ __launch_bounds__(256)
void fill_kernel(const void* __restrict__ ei_raw, int E) {
    int e = blockIdx.x * blockDim.x + threadIdx.x;
    if (e >= E) return;
    int src = load_idx(ei_raw, E, 0, e);
    int dst = load_idx(ei_raw, E, 1, e);
    int pos = atomicAdd(&g_cursor[dst], 1);
    g_csr_src[pos] = src;
}

// ---------------------------------------------------------------------------
// Gather-accumulate: h[n] = sum over incoming edges of m[src].
// One warp per dst node; each lane owns one float4 (512 B/row, coalesced).
// Plain store — no atomics. Isolated nodes get exact zeros.
// ---------------------------------------------------------------------------
__global__ __launch_bounds__(256)
void gather_sum_kernel(const float* __restrict__ M, float* __restrict__ H) {
    int node = (blockIdx.x * blockDim.x + threadIdx.x) >> 5;
    if (node >= NNODES) return;
    int lane = threadIdx.x & 31;

    int e   = g_row_start[node];
    int end = g_row_start[node + 1];

    float4 acc0 = make_float4(0.f, 0.f, 0.f, 0.f);
    float4 acc1 = make_float4(0.f, 0.f, 0.f, 0.f);

    for (; e + 1 < end; e += 2) {
        int s0 = __ldg(g_csr_src + e);
        int s1 = __ldg(g_csr_src + e + 1);
        float4 v0 = *reinterpret_cast<const float4*>(M + (size_t)s0 * DIM + lane * 4);
        float4 v1 = *reinterpret_cast<const float4*>(M + (size_t)s1 * DIM + lane * 4);
        acc0.x += v0.x; acc0.y += v0.y; acc0.z += v0.z; acc0.w += v0.w;
        acc1.x += v1.x; acc1.y += v1.y; acc1.z += v1.z; acc1.w += v1.w;
    }
    if (e < end) {
        int s0 = __ldg(g_csr_src + e);
        float4 v0 = *reinterpret_cast<const float4*>(M + (size_t)s0 * DIM + lane * 4);
        acc0.x += v0.x; acc0.y += v0.y; acc0.z += v0.z; acc0.w += v0.w;
    }

    float4 o;
    o.x = acc0.x + acc1.x; o.y = acc0.y + acc1.y;
    o.z = acc0.z + acc1.z; o.w = acc0.w + acc1.w;
    *reinterpret_cast<float4*>(H + (size_t)node * DIM + lane * 4) = o;
}

// ---------------------------------------------------------------------------
// Tiled fp32 GEMM (round-5 winner, ZERO_H removed):
//   C[N x BN] = op(A)[N x 128] @ W[128 x BN] + bias ; op = relu if RELU_IN.
// BM=64, BK=32, TM=8, TN=4. THREADS = 8 * (BN/4).
// ---------------------------------------------------------------------------
template <int BN, bool RELU_IN>
__global__ __launch_bounds__((64 / 8) * (BN / 4))
void gemm_kernel(const float* __restrict__ A,
                 const float* __restrict__ W,
                 const float* __restrict__ bias,
                 float* __restrict__ C,
                 int Nrows) {
    constexpr int BM = 64;
    constexpr int BK = 32;
    constexpr int TM = 8;
    constexpr int TN = 4;
    constexpr int THREADS = (BM / TM) * (BN / TN);

    __shared__ float As[BK][BM + 4];   // transposed A tile
    __shared__ float Ws[BK][BN];       // W tile

    const int tid = threadIdx.x;
    const int rb  = blockIdx.x * BM;

    const int ty = tid / (BN / TN);    // 0..7
    const int tx = tid % (BN / TN);
    const int m0 = ty * TM;
    const int n0 = tx * TN;

    float acc[TM][TN];
    #pragma unroll
    for (int i = 0; i < TM; i++)
        #pragma unroll
        for (int j = 0; j < TN; j++) acc[i][j] = 0.0f;

    for (int k0 = 0; k0 < DIM; k0 += BK) {
        // ---- load A tile (transposed into smem), optional ReLU ----
        #pragma unroll
        for (int q = tid; q < BM * (BK / 4); q += THREADS) {
            int r  = q >> 3;          // BK/4 == 8
            int c4 = q & 7;
            int row = rb + r;
            float4 v = make_float4(0.f, 0.f, 0.f, 0.f);
            if (row < Nrows)
                v = *reinterpret_cast<const float4*>(
                        A + (size_t)row * DIM + k0 + c4 * 4);
            if (RELU_IN) {
                v.x = fmaxf(v.x, 0.f); v.y = fmaxf(v.y, 0.f);
                v.z = fmaxf(v.z, 0.f); v.w = fmaxf(v.w, 0.f);
            }
            As[c4 * 4 + 0][r] = v.x;
            As[c4 * 4 + 1][r] = v.y;
            As[c4 * 4 + 2][r] = v.z;
            As[c4 * 4 + 3][r] = v.w;
        }
        // ---- load W tile ----
        #pragma unroll
        for (int q = tid; q < BK * (BN / 4); q += THREADS) {
            int kk = q / (BN / 4);
            int n4 = q % (BN / 4);
            float4 v = *reinterpret_cast<const float4*>(
                W + (size_t)(k0 + kk) * BN + n4 * 4);
            *reinterpret_cast<float4*>(&Ws[kk][n4 * 4]) = v;
        }
        __syncthreads();

        // ---- compute ----
        #pragma unroll
        for (int kk = 0; kk < BK; kk++) {
            float4 a0 = *reinterpret_cast<const float4*>(&As[kk][m0]);
            float4 a1 = *reinterpret_cast<const float4*>(&As[kk][m0 + 4]);
            float4 w  = *reinterpret_cast<const float4*>(&Ws[kk][n0]);
            float av[TM] = {a0.x, a0.y, a0.z, a0.w, a1.x, a1.y, a1.z, a1.w};
            float wv[TN] = {w.x, w.y, w.z, w.w};
            #pragma unroll
            for (int i = 0; i < TM; i++)
                #pragma unroll
                for (int j = 0; j < TN; j++)
                    acc[i][j] = fmaf(av[i], wv[j], acc[i][j]);
        }
        __syncthreads();
    }

    // ---- epilogue: bias add, store C ----
    const float4 bb = *reinterpret_cast<const float4*>(bias + n0);
    #pragma unroll
    for (int i = 0; i < TM; i++) {
        int row = rb + m0 + i;
        if (row < Nrows) {
            float4 o;
            o.x = acc[i][0] + bb.x;
            o.y = acc[i][1] + bb.y;
            o.z = acc[i][2] + bb.z;
            o.w = acc[i][3] + bb.w;
            *reinterpret_cast<float4*>(C + (size_t)row * BN + n0) = o;
        }
    }
}

// ---------------------------------------------------------------------------
// Launch sequence:
//   build CSR(dst -> srcs)                         [once, reused 4x]
//   m = x @ W1 + b1        ; h = gather(m)
//   m = h @ W1 + b1        ; h = gather(m)
//   m = relu(h) @ W2 + b2  ; h = gather(m)
//   m = h @ W2 + b2        ; h = gather(m)
//   out = relu(h) @ Wout + bout
// ---------------------------------------------------------------------------
extern "C" void kernel_launch(void* const* d_in, const int* in_sizes, int n_in,
                              void* d_out, int out_size) {
    const float* x    = (const float*)d_in[0];
    const void*  ei   = (const void*)d_in[1];
    const float* W1   = (const float*)d_in[2];
    const float* b1   = (const float*)d_in[3];
    const float* W2   = (const float*)d_in[4];
    const float* b2   = (const float*)d_in[5];
    const float* Wout = (const float*)d_in[6];
    const float* bout = (const float*)d_in[7];
    float* out = (float*)d_out;

    float *m_ptr = nullptr, *h_ptr = nullptr;
    cudaGetSymbolAddress((void**)&m_ptr, g_m);
    cudaGetSymbolAddress((void**)&h_ptr, g_h);

    const int N = NNODES;
    const int E = NEDGES;

    const int gemm_blocks   = (N + 63) / 64;        // 782
    const int edge_blocks   = (E + 255) / 256;      // 2344
    const int gather_blocks = (N + 7) / 8;          // 8 warps (nodes) / block

    // ---- CSR build (once per call; no caching) ----
    detect_idx_width_kernel<<<1, 32>>>((const int*)ei);
    zero_deg_kernel<<<(NPAD + 255) / 256, 256>>>();
    hist_kernel<<<edge_blocks, 256>>>(ei, E);
    scan1_kernel<<<SCAN_BLOCKS, 1024>>>();
    scan2_kernel<<<1, 32>>>();
    scan3_kernel<<<SCAN_BLOCKS, 1024>>>();
    fill_kernel<<<edge_blocks, 256>>>(ei, E);

    // ---- pool layer 1 (W1) x2 ----
    gemm_kernel<128, false><<<gemm_blocks, 256>>>(x, W1, b1, m_ptr, N);
    gather_sum_kernel<<<gather_blocks, 256>>>(m_ptr, h_ptr);
    gemm_kernel<128, false><<<gemm_blocks, 256>>>(h_ptr, W1, b1, m_ptr, N);
    gather_sum_kernel<<<gather_blocks, 256>>>(m_ptr, h_ptr);

    // ---- relu + pool layer 2 (W2) x2 ----
    gemm_kernel<128, true><<<gemm_blocks, 256>>>(h_ptr, W2, b2, m_ptr, N);
    gather_sum_kernel<<<gather_blocks, 256>>>(m_ptr, h_ptr);
    gemm_kernel<128, false><<<gemm_blocks, 256>>>(h_ptr, W2, b2, m_ptr, N);
    gather_sum_kernel<<<gather_blocks, 256>>>(m_ptr, h_ptr);

    // ---- relu + output projection ----
    gemm_kernel<64, true><<<gemm_blocks, 128>>>(h_ptr, Wout, bout, out, N);
}

// round 15
// speedup vs baseline: 1.0026x; 1.0026x over previous
#include <cuda_runtime.h>
#include <cuda_bf16.h>
#include <cstdint>

// Problem constants (fixed by the reference)
#define NNODES 50000
#define NEDGES 600000
#define DIM    128
#define OUTD   64

#define SCAN_BLOCKS 49           // 49 * 1024 = 50176 >= NNODES
#define NPAD (SCAN_BLOCKS * 1024)

// Scratch (no cudaMalloc allowed)
__device__ float g_m[(size_t)NNODES * DIM];   // GEMM output  (25.6 MB)
__device__ float g_h[(size_t)NNODES * DIM];   // gather dest  (25.6 MB)
__device__ int   g_is64;                      // edge_index dtype flag

// CSR-by-dst scratch
__device__ int g_deg[NPAD];
__device__ int g_excl[NPAD];                  // per-block exclusive scan
__device__ int g_bsum[SCAN_BLOCKS];
__device__ int g_bpre[SCAN_BLOCKS + 1];
__device__ int g_row_start[NNODES + 1];
__device__ int g_cursor[NNODES];
__device__ int g_csr_src[NEDGES];

// ---------------------------------------------------------------------------
// Detect whether edge_index is int64 or int32.
// int64 values in [0, 50000): every odd int32 word is 0 (little-endian).
// ---------------------------------------------------------------------------
__global__ void detect_idx_width_kernel(const int* __restrict__ ei32) {
    if (threadIdx.x == 0 && blockIdx.x == 0) {
        int acc = 0;
        #pragma unroll
        for (int i = 0; i < 16; i++) acc |= ei32[2 * i + 1];
        g_is64 = (acc == 0) ? 1 : 0;
    }
}

__device__ __forceinline__ int load_idx(const void* ei_raw, int E, int half, int e) {
    if (g_is64) {
        const long long* ei = (const long long*)ei_raw;
        return (int)__ldg(ei + (size_t)half * E + e);
    } else {
        const int* ei = (const int*)ei_raw;
        return __ldg(ei + (size_t)half * E + e);
    }
}

// ---------------------------------------------------------------------------
// CSR build kernels
// ---------------------------------------------------------------------------
__global__ void zero_deg_kernel() {
    int i = blockIdx.x * blockDim.x + threadIdx.x;
    if (i < NPAD) g_deg[i] = 0;
}

__global__ __launch_bounds__(256)
void hist_kernel(const void* __restrict__ ei_raw, int E) {
    int e = blockIdx.x * blockDim.x + threadIdx.x;
    if (e >= E) return;
    int dst = load_idx(ei_raw, E, 1, e);
    atomicAdd(&g_deg[dst], 1);
}

// per-1024-block inclusive scan of g_deg (Hillis-Steele); store exclusive.
__global__ __launch_bounds__(1024)
void scan1_kernel() {
    __shared__ int sm[1024];
    int i = blockIdx.x * 1024 + threadIdx.x;
    int v = g_deg[i];
    sm[threadIdx.x] = v;
    __syncthreads();
    #pragma unroll
    for (int off = 1; off < 1024; off <<= 1) {
        int t = (threadIdx.x >= off) ? sm[threadIdx.x - off] : 0;
        __syncthreads();
        sm[threadIdx.x] += t;
        __syncthreads();
    }
    g_excl[i] = sm[threadIdx.x] - v;
    if (threadIdx.x == 1023) g_bsum[blockIdx.x] = sm[1023];
}

__global__ void scan2_kernel() {
    if (threadIdx.x == 0 && blockIdx.x == 0) {
        int run = 0;
        #pragma unroll
        for (int b = 0; b < SCAN_BLOCKS; b++) {
            g_bpre[b] = run;
            run += g_bsum[b];
        }
        g_bpre[SCAN_BLOCKS] = run;
        g_row_start[NNODES] = run;   // == NEDGES
    }
}

__global__ __launch_bounds__(1024)
void scan3_kernel() {
    int i = blockIdx.x * 1024 + threadIdx.x;
    if (i < NNODES) {
        int rs = g_excl[i] + g_bpre[blockIdx.x];
        g_row_start[i] = rs;
        g_cursor[i]    = rs;
    }
}

__global__ __launch_bounds__(256)
void fill_kernel(const void* __restrict__ ei_raw, int E) {
    int e = blockIdx.x * blockDim.x + threadIdx.x;
    if (e >= E) return;
    int src = load_idx(ei_raw, E, 0, e);
    int dst = load_idx(ei_raw, E, 1, e);
    int pos = atomicAdd(&g_cursor[dst], 1);
    g_csr_src[pos] = src;
}

// ---------------------------------------------------------------------------
// Gather-accumulate: h[n] = sum over incoming edges of m[src].
// One warp per dst node; each lane owns one float4 (512 B/row, coalesced).
// Plain store — no atomics. Isolated nodes get exact zeros.
// ---------------------------------------------------------------------------
__global__ __launch_bounds__(256)
void gather_sum_kernel(const float* __restrict__ M, float* __restrict__ H) {
    int node = (blockIdx.x * blockDim.x + threadIdx.x) >> 5;
    if (node >= NNODES) return;
    int lane = threadIdx.x & 31;

    int e   = g_row_start[node];
    int end = g_row_start[node + 1];

    float4 acc0 = make_float4(0.f, 0.f, 0.f, 0.f);
    float4 acc1 = make_float4(0.f, 0.f, 0.f, 0.f);

    for (; e + 1 < end; e += 2) {
        int s0 = __ldg(g_csr_src + e);
        int s1 = __ldg(g_csr_src + e + 1);
        float4 v0 = *reinterpret_cast<const float4*>(M + (size_t)s0 * DIM + lane * 4);
        float4 v1 = *reinterpret_cast<const float4*>(M + (size_t)s1 * DIM + lane * 4);
        acc0.x += v0.x; acc0.y += v0.y; acc0.z += v0.z; acc0.w += v0.w;
        acc1.x += v1.x; acc1.y += v1.y; acc1.z += v1.z; acc1.w += v1.w;
    }
    if (e < end) {
        int s0 = __ldg(g_csr_src + e);
        float4 v0 = *reinterpret_cast<const float4*>(M + (size_t)s0 * DIM + lane * 4);
        acc0.x += v0.x; acc0.y += v0.y; acc0.z += v0.z; acc0.w += v0.w;
    }

    float4 o;
    o.x = acc0.x + acc1.x; o.y = acc0.y + acc1.y;
    o.z = acc0.z + acc1.z; o.w = acc0.w + acc1.w;
    *reinterpret_cast<float4*>(H + (size_t)node * DIM + lane * 4) = o;
}

// ---------------------------------------------------------------------------
// Tiled fp32 GEMM (round-5 winner, ZERO_H removed):
//   C[N x BN] = op(A)[N x 128] @ W[128 x BN] + bias ; op = relu if RELU_IN.
// BM=64, BK=32, TM=8, TN=4. THREADS = 8 * (BN/4).
// ---------------------------------------------------------------------------
template <int BN, bool RELU_IN>
__global__ __launch_bounds__((64 / 8) * (BN / 4))
void gemm_kernel(const float* __restrict__ A,
                 const float* __restrict__ W,
                 const float* __restrict__ bias,
                 float* __restrict__ C,
                 int Nrows) {
    constexpr int BM = 64;
    constexpr int BK = 32;
    constexpr int TM = 8;
    constexpr int TN = 4;
    constexpr int THREADS = (BM / TM) * (BN / TN);

    __shared__ float As[BK][BM + 4];   // transposed A tile
    __shared__ float Ws[BK][BN];       // W tile

    const int tid = threadIdx.x;
    const int rb  = blockIdx.x * BM;

    const int ty = tid / (BN / TN);    // 0..7
    const int tx = tid % (BN / TN);
    const int m0 = ty * TM;
    const int n0 = tx * TN;

    float acc[TM][TN];
    #pragma unroll
    for (int i = 0; i < TM; i++)
        #pragma unroll
        for (int j = 0; j < TN; j++) acc[i][j] = 0.0f;

    for (int k0 = 0; k0 < DIM; k0 += BK) {
        // ---- load A tile (transposed into smem), optional ReLU ----
        #pragma unroll
        for (int q = tid; q < BM * (BK / 4); q += THREADS) {
            int r  = q >> 3;          // BK/4 == 8
            int c4 = q & 7;
            int row = rb + r;
            float4 v = make_float4(0.f, 0.f, 0.f, 0.f);
            if (row < Nrows)
                v = *reinterpret_cast<const float4*>(
                        A + (size_t)row * DIM + k0 + c4 * 4);
            if (RELU_IN) {
                v.x = fmaxf(v.x, 0.f); v.y = fmaxf(v.y, 0.f);
                v.z = fmaxf(v.z, 0.f); v.w = fmaxf(v.w, 0.f);
            }
            As[c4 * 4 + 0][r] = v.x;
            As[c4 * 4 + 1][r] = v.y;
            As[c4 * 4 + 2][r] = v.z;
            As[c4 * 4 + 3][r] = v.w;
        }
        // ---- load W tile ----
        #pragma unroll
        for (int q = tid; q < BK * (BN / 4); q += THREADS) {
            int kk = q / (BN / 4);
            int n4 = q % (BN / 4);
            float4 v = *reinterpret_cast<const float4*>(
                W + (size_t)(k0 + kk) * BN + n4 * 4);
            *reinterpret_cast<float4*>(&Ws[kk][n4 * 4]) = v;
        }
        __syncthreads();

        // ---- compute ----
        #pragma unroll
        for (int kk = 0; kk < BK; kk++) {
            float4 a0 = *reinterpret_cast<const float4*>(&As[kk][m0]);
            float4 a1 = *reinterpret_cast<const float4*>(&As[kk][m0 + 4]);
            float4 w  = *reinterpret_cast<const float4*>(&Ws[kk][n0]);
            float av[TM] = {a0.x, a0.y, a0.z, a0.w, a1.x, a1.y, a1.z, a1.w};
            float wv[TN] = {w.x, w.y, w.z, w.w};
            #pragma unroll
            for (int i = 0; i < TM; i++)
                #pragma unroll
                for (int j = 0; j < TN; j++)
                    acc[i][j] = fmaf(av[i], wv[j], acc[i][j]);
        }
        __syncthreads();
    }

    // ---- epilogue: bias add, store C ----
    const float4 bb = *reinterpret_cast<const float4*>(bias + n0);
    #pragma unroll
    for (int i = 0; i < TM; i++) {
        int row = rb + m0 + i;
        if (row < Nrows) {
            float4 o;
            o.x = acc[i][0] + bb.x;
            o.y = acc[i][1] + bb.y;
            o.z = acc[i][2] + bb.z;
            o.w = acc[i][3] + bb.w;
            *reinterpret_cast<float4*>(C + (size_t)row * BN + n0) = o;
        }
    }
}

// ---------------------------------------------------------------------------
// Launch sequence:
//   build CSR(dst -> srcs)                         [once, reused 4x]
//   m = x @ W1 + b1        ; h = gather(m)
//   m = h @ W1 + b1        ; h = gather(m)
//   m = relu(h) @ W2 + b2  ; h = gather(m)
//   m = h @ W2 + b2        ; h = gather(m)
//   out = relu(h) @ Wout + bout
// ---------------------------------------------------------------------------
extern "C" void kernel_launch(void* const* d_in, const int* in_sizes, int n_in,
                              void* d_out, int out_size) {
    const float* x    = (const float*)d_in[0];
    const void*  ei   = (const void*)d_in[1];
    const float* W1   = (const float*)d_in[2];
    const float* b1   = (const float*)d_in[3];
    const float* W2   = (const float*)d_in[4];
    const float* b2   = (const float*)d_in[5];
    const float* Wout = (const float*)d_in[6];
    const float* bout = (const float*)d_in[7];
    float* out = (float*)d_out;

    float *m_ptr = nullptr, *h_ptr = nullptr;
    cudaGetSymbolAddress((void**)&m_ptr, g_m);
    cudaGetSymbolAddress((void**)&h_ptr, g_h);

    const int N = NNODES;
    const int E = NEDGES;

    const int gemm_blocks   = (N + 63) / 64;        // 782
    const int edge_blocks   = (E + 255) / 256;      // 2344
    const int gather_blocks = (N + 7) / 8;          // 8 warps (nodes) / block

    // ---- CSR build (once per call; no caching) ----
    detect_idx_width_kernel<<<1, 32>>>((const int*)ei);
    zero_deg_kernel<<<(NPAD + 255) / 256, 256>>>();
    hist_kernel<<<edge_blocks, 256>>>(ei, E);
    scan1_kernel<<<SCAN_BLOCKS, 1024>>>();
    scan2_kernel<<<1, 32>>>();
    scan3_kernel<<<SCAN_BLOCKS, 1024>>>();
    fill_kernel<<<edge_blocks, 256>>>(ei, E);

    // ---- pool layer 1 (W1) x2 ----
    gemm_kernel<128, false><<<gemm_blocks, 256>>>(x, W1, b1, m_ptr, N);
    gather_sum_kernel<<<gather_blocks, 256>>>(m_ptr, h_ptr);
    gemm_kernel<128, false><<<gemm_blocks, 256>>>(h_ptr, W1, b1, m_ptr, N);
    gather_sum_kernel<<<gather_blocks, 256>>>(m_ptr, h_ptr);

    // ---- relu + pool layer 2 (W2) x2 ----
    gemm_kernel<128, true><<<gemm_blocks, 256>>>(h_ptr, W2, b2, m_ptr, N);
    gather_sum_kernel<<<gather_blocks, 256>>>(m_ptr, h_ptr);
    gemm_kernel<128, false><<<gemm_blocks, 256>>>(h_ptr, W2, b2, m_ptr, N);
    gather_sum_kernel<<<gather_blocks, 256>>>(m_ptr, h_ptr);

    // ---- relu + output projection ----
    gemm_kernel<64, true><<<gemm_blocks, 128>>>(h_ptr, Wout, bout, out, N);
}